// round 9
// baseline (speedup 1.0000x reference)
#include <cuda_runtime.h>
#include <cuda_fp16.h>
#include <cstdint>

// ============================================================================
// Attention_32916629357041 — fp16 2-term split GEMMs (mma.sync, sm_100 base)
//   prep:  x -> fp16 hi/lo; w_qkv (q-rows pre-scaled), w_out -> single fp16
//   gemm1: qkv = x @ w_qkv^T   (2 mma terms: Ah*B + Al*B, fp32 acc)
//   attn:  per-window softmax core (fp32, writes ao as fp16 hi/lo)
//   gemm2: y = ao @ w_out^T + b_out
// R9: CTA 256x128, warp tile 64x64, 1 CTA/SM (255 regs) — cuts ldmatrix
//     traffic from 0.125 to 0.02 B/MAC (smem crossbar was the binding limit).
// ============================================================================

typedef unsigned long long ull;

#define NB    1024
#define NTOK  64
#define DIM   512
#define QKDIM 1536
#define NROWS (NB * NTOK)          // 65536
#define SCALE 0.125f

// ---------------- device scratch ----------------
__device__ __half g_x_h[(size_t)NROWS * DIM];
__device__ __half g_x_l[(size_t)NROWS * DIM];
__device__ __half g_w1[QKDIM * DIM];
__device__ __half g_w2[DIM * DIM];
__device__ float  g_qkv[(size_t)NROWS * QKDIM];
__device__ __half g_ao_h[(size_t)NROWS * DIM];
__device__ __half g_ao_l[(size_t)NROWS * DIM];

// ---------------- helpers ----------------
__device__ __forceinline__ ull pk2(float x, float y) {
    ull r; asm("mov.b64 %0, {%1, %2};" : "=l"(r) : "f"(x), "f"(y)); return r;
}
__device__ __forceinline__ void fma2(ull& d, ull a, ull b) {
    asm("fma.rn.f32x2 %0, %1, %2, %0;" : "+l"(d) : "l"(a), "l"(b));
}
__device__ __forceinline__ float2 up2(ull v) {
    float2 f; asm("mov.b64 {%0, %1}, %2;" : "=f"(f.x), "=f"(f.y) : "l"(v)); return f;
}
__device__ __forceinline__ uint32_t smem_u32(const void* p) {
    uint32_t a;
    asm("{ .reg .u64 t; cvta.to.shared.u64 t, %1; cvt.u32.u64 %0, t; }" : "=r"(a) : "l"(p));
    return a;
}
__device__ __forceinline__ void cpa16(uint32_t dst, const void* src) {
    asm volatile("cp.async.cg.shared.global [%0], [%1], 16;" :: "r"(dst), "l"(src));
}
__device__ __forceinline__ void cpa_commit() {
    asm volatile("cp.async.commit_group;" ::: "memory");
}
template <int N>
__device__ __forceinline__ void cpa_wait() {
    asm volatile("cp.async.wait_group %0;" :: "n"(N) : "memory");
}
__device__ __forceinline__ void ldsm4(uint32_t* r, uint32_t addr) {
    asm volatile("ldmatrix.sync.aligned.m8n8.x4.shared.b16 {%0,%1,%2,%3}, [%4];"
                 : "=r"(r[0]), "=r"(r[1]), "=r"(r[2]), "=r"(r[3]) : "r"(addr));
}
__device__ __forceinline__ void mma16816(float* c, const uint32_t* a, const uint32_t* b) {
    asm volatile(
        "mma.sync.aligned.m16n8k16.row.col.f32.f16.f16.f32 "
        "{%0,%1,%2,%3}, {%4,%5,%6,%7}, {%8,%9}, {%0,%1,%2,%3};"
        : "+f"(c[0]), "+f"(c[1]), "+f"(c[2]), "+f"(c[3])
        : "r"(a[0]), "r"(a[1]), "r"(a[2]), "r"(a[3]), "r"(b[0]), "r"(b[1]));
}

// ============================================================================
// prep
// ============================================================================
__global__ void prep_kernel(const float* __restrict__ x,
                            const float* __restrict__ w1,
                            const float* __restrict__ w2) {
    size_t stride = (size_t)gridDim.x * blockDim.x;
    size_t tid = (size_t)blockIdx.x * blockDim.x + threadIdx.x;
    for (size_t i = tid; i < (size_t)NROWS * DIM; i += stride) {
        float v = x[i];
        __half h = __float2half(v);
        g_x_h[i] = h;
        g_x_l[i] = __float2half(v - __half2float(h));
    }
    for (size_t i = tid; i < (size_t)QKDIM * DIM; i += stride) {
        float v = w1[i] * ((i < (size_t)DIM * DIM) ? SCALE : 1.0f);  // fold q-scale
        g_w1[i] = __float2half(v);
    }
    for (size_t i = tid; i < (size_t)DIM * DIM; i += stride)
        g_w2[i] = __float2half(w2[i]);
}

// ============================================================================
// gemm: C[m][n] = sum_k A[m][k]*B[n][k], K=512, A fp16 hi/lo 2-term, fp32 acc
// CTA tile 256x128, 8 warps (4M x 2N), warp tile 64x64. k-chunk 32,
// 3-stage cp.async pipeline, one __syncthreads per chunk. 1 CTA/SM.
// ============================================================================
#define KC    32
#define ROWB  80                  // bytes per smem row (32 fp16 + 16 pad)
#define AMATB (256 * ROWB)        // 20480 per A matrix (256 rows)
#define BMATB (128 * ROWB)        // 10240 for B (128 rows)
#define STG   (2 * AMATB + BMATB) // Ah Al B per stage = 51200
#define GSMEM (3 * STG)           // 153600 (3 stages)

struct GemmSrc { const __half *Ah, *Al, *B; };

__device__ __forceinline__ void issue_stage(const GemmSrc& S, size_t arow0,
                                            size_t brow0, int kc, uint32_t sb,
                                            int t) {
    // A_hi, A_lo: 256 rows x 4 c16 = 1024 cpa16 each (4 per thread)
    #pragma unroll
    for (int m = 0; m < 2; ++m) {
        const __half* mat = m ? S.Al : S.Ah;
        #pragma unroll
        for (int l = 0; l < 4; ++l) {
            int idx = t + l * 256;            // 0..1023
            int r = idx >> 2, c16 = idx & 3;
            cpa16(sb + m * AMATB + r * ROWB + c16 * 16,
                  mat + (arow0 + r) * DIM + kc * KC + c16 * 8);
        }
    }
    // B: 128 rows x 4 c16 = 512 cpa16 (2 per thread)
    #pragma unroll
    for (int l = 0; l < 2; ++l) {
        int idx = t + l * 256;                // 0..511
        int r = idx >> 2, c16 = idx & 3;
        cpa16(sb + 2 * AMATB + r * ROWB + c16 * 16,
              S.B + (brow0 + r) * DIM + kc * KC + c16 * 8);
    }
    cpa_commit();
}

__global__ void __launch_bounds__(256, 1)
gemm_kernel(int which, const float* __restrict__ bias, float* __restrict__ cext) {
    extern __shared__ char sm[];
    const uint32_t sbase = smem_u32(sm);

    const int t = threadIdx.x, w = t >> 5, lane = t & 31;
    const int wm = w & 3, wn = w >> 2;
    const int nt = blockIdx.x, rt = blockIdx.y;

    GemmSrc S;
    float* C; int ldc;
    if (which == 0) { S = {g_x_h,  g_x_l,  g_w1};
                      C = g_qkv; ldc = QKDIM; }
    else            { S = {g_ao_h, g_ao_l, g_w2};
                      C = cext;  ldc = DIM; }
    const size_t arow0 = (size_t)rt * 256;
    const size_t brow0 = (size_t)nt * 128;

    float acc[4][8][4];
    #pragma unroll
    for (int mi = 0; mi < 4; ++mi)
        #pragma unroll
        for (int ni = 0; ni < 8; ++ni)
            #pragma unroll
            for (int e = 0; e < 4; ++e) acc[mi][ni][e] = 0.f;

    // ldmatrix lane addressing
    const int a_row  = wm * 64 + (lane & 15);
    const int a_koff = (lane >> 4) * 16;
    const int b_lr = lane & 7, b_g2 = lane >> 3;
    const int b_nrow_base = wn * 64 + b_lr + (b_g2 >> 1) * 8;
    const int b_koff = (b_g2 & 1) * 16;

    const int NKC = DIM / KC;   // 16
    issue_stage(S, arow0, brow0, 0, sbase, t);
    issue_stage(S, arow0, brow0, 1, sbase + STG, t);

    for (int kc = 0; kc < NKC; ++kc) {
        const uint32_t sb = sbase + (kc % 3) * STG;
        if (kc + 1 < NKC) cpa_wait<1>();   // stage kc landed; kc+1 may pend
        else              cpa_wait<0>();
        __syncthreads();                   // data visible; buf (kc+2)%3 free
        if (kc + 2 < NKC)
            issue_stage(S, arow0, brow0, kc + 2, sbase + ((kc + 2) % 3) * STG, t);

        #pragma unroll
        for (int k16 = 0; k16 < 2; ++k16) {
            const int kb = k16 * 32;      // byte offset of this k16 in the row
            // hold all B fragments (reused across 4 A sub-tiles)
            uint32_t bb[4][4];
            #pragma unroll
            for (int g = 0; g < 4; ++g)
                ldsm4(bb[g], sb + 2 * AMATB +
                              (b_nrow_base + g * 16) * ROWB + kb + b_koff);
            // JIT A: per mi load hi+lo, fire 16 mmas
            #pragma unroll
            for (int mi = 0; mi < 4; ++mi) {
                uint32_t ah[4], al[4];
                uint32_t ad = sb + (a_row + mi * 16) * ROWB + kb + a_koff;
                ldsm4(ah, ad);
                ldsm4(al, ad + AMATB);
                #pragma unroll
                for (int g = 0; g < 4; ++g) {
                    mma16816(acc[mi][2 * g],     ah, bb[g]);
                    mma16816(acc[mi][2 * g + 1], ah, bb[g] + 2);
                    mma16816(acc[mi][2 * g],     al, bb[g]);
                    mma16816(acc[mi][2 * g + 1], al, bb[g] + 2);
                }
            }
        }
    }

    // ---- epilogue: direct register -> gmem stores ----
    const int qr = lane >> 2, qc = lane & 3;
    #pragma unroll
    for (int mi = 0; mi < 4; ++mi) {
        #pragma unroll
        for (int ni = 0; ni < 8; ++ni) {
            size_t row = arow0 + wm * 64 + mi * 16 + qr;
            int col = nt * 128 + wn * 64 + ni * 8 + qc * 2;
            float2 v0 = make_float2(acc[mi][ni][0], acc[mi][ni][1]);
            float2 v1 = make_float2(acc[mi][ni][2], acc[mi][ni][3]);
            if (bias != nullptr) {
                float2 bz = *(const float2*)(bias + col);
                v0.x += bz.x; v0.y += bz.y; v1.x += bz.x; v1.y += bz.y;
            }
            *(float2*)(C + row * ldc + col)       = v0;
            *(float2*)(C + (row + 8) * ldc + col) = v1;
        }
    }
}

// ============================================================================
// attention core: per window, fp32. Reads g_qkv, writes g_ao_{h,l} (fp16).
// ============================================================================
#define AQ 68
#define ASMEM ((4 * 64 * AQ + 240) * 4)

__global__ void __launch_bounds__(256, 2)
attn_kernel(const float* __restrict__ Mat) {
    extern __shared__ float smf[];
    float* qs   = smf;
    float* ks   = qs + 64 * AQ;
    float* vs   = ks + 64 * AQ;
    float* as_  = vs + 64 * AQ;
    float* mats = as_ + 64 * AQ;

    const int b = blockIdx.x, t = threadIdx.x;
    if (t < 225) mats[t] = Mat[t];

    const int tx = t & 15, ty = t >> 4;
    const int ai0 = ty * 4, tj = tx, d0 = tx * 4;
    const float* qg = g_qkv + (size_t)b * NTOK * QKDIM;

    for (int h = 0; h < 8; ++h) {
        #pragma unroll
        for (int l = 0; l < 4; ++l) {
            int idx = t + l * 256;           // 0..1023
            int row = idx >> 4, c4 = idx & 15;
            const float* rp = qg + (size_t)row * QKDIM + h * 64 + c4 * 4;
            *(float4*)(qs + row * AQ + c4 * 4) = *(const float4*)(rp);
            *(float4*)(ks + row * AQ + c4 * 4) = *(const float4*)(rp + 512);
            *(float4*)(vs + row * AQ + c4 * 4) = *(const float4*)(rp + 1024);
        }
        __syncthreads();

        // ---- sim = q k^T + bias; softmax ----
        {
            ull s2[4][4];
            #pragma unroll
            for (int r = 0; r < 4; ++r)
                #pragma unroll
                for (int c = 0; c < 4; ++c) s2[r][c] = 0ULL;

            #pragma unroll 4
            for (int dq = 0; dq < 16; ++dq) {
                float4 qv[4], kv[4];
                #pragma unroll
                for (int r = 0; r < 4; ++r)
                    qv[r] = *(const float4*)(qs + (ai0 + r) * AQ + 4 * dq);
                #pragma unroll
                for (int c = 0; c < 4; ++c)
                    kv[c] = *(const float4*)(ks + (tj + 16 * c) * AQ + 4 * dq);
                #pragma unroll
                for (int r = 0; r < 4; ++r) {
                    ull q01 = pk2(qv[r].x, qv[r].y), q23 = pk2(qv[r].z, qv[r].w);
                    #pragma unroll
                    for (int c = 0; c < 4; ++c) {
                        fma2(s2[r][c], q01, pk2(kv[c].x, kv[c].y));
                        fma2(s2[r][c], q23, pk2(kv[c].z, kv[c].w));
                    }
                }
            }
            #pragma unroll
            for (int r = 0; r < 4; ++r) {
                int i = ai0 + r;
                int r1 = i >> 3, c1 = i & 7;
                float sim[4];
                #pragma unroll
                for (int c = 0; c < 4; ++c) {
                    int j = tj + 16 * c;
                    int r2 = j >> 3, c2 = j & 7;
                    float2 p = up2(s2[r][c]);
                    sim[c] = p.x + p.y + mats[(r2 - r1 + 7) * 15 + (c2 - c1 + 7)];
                }
                float m = fmaxf(fmaxf(sim[0], sim[1]), fmaxf(sim[2], sim[3]));
                m = fmaxf(m, __shfl_xor_sync(0xffffffffu, m, 1));
                m = fmaxf(m, __shfl_xor_sync(0xffffffffu, m, 2));
                m = fmaxf(m, __shfl_xor_sync(0xffffffffu, m, 4));
                m = fmaxf(m, __shfl_xor_sync(0xffffffffu, m, 8));
                float e0 = __expf(sim[0] - m), e1 = __expf(sim[1] - m);
                float e2 = __expf(sim[2] - m), e3 = __expf(sim[3] - m);
                float s = e0 + e1 + e2 + e3;
                s += __shfl_xor_sync(0xffffffffu, s, 1);
                s += __shfl_xor_sync(0xffffffffu, s, 2);
                s += __shfl_xor_sync(0xffffffffu, s, 4);
                s += __shfl_xor_sync(0xffffffffu, s, 8);
                float inv = 1.f / s;
                as_[(ai0 + r) * AQ + tj]      = e0 * inv;
                as_[(ai0 + r) * AQ + tj + 16] = e1 * inv;
                as_[(ai0 + r) * AQ + tj + 32] = e2 * inv;
                as_[(ai0 + r) * AQ + tj + 48] = e3 * inv;
            }
        }
        __syncthreads();

        // ---- out = attn @ v ; split to fp16 hi/lo ----
        {
            ull o2[4][2];
            #pragma unroll
            for (int r = 0; r < 4; ++r) { o2[r][0] = 0ULL; o2[r][1] = 0ULL; }
            #pragma unroll 4
            for (int j = 0; j < 64; ++j) {
                float4 vv = *(const float4*)(vs + j * AQ + d0);
                ull vp0 = pk2(vv.x, vv.y), vp1 = pk2(vv.z, vv.w);
                #pragma unroll
                for (int r = 0; r < 4; ++r) {
                    float a = as_[(ai0 + r) * AQ + j];
                    ull pa = pk2(a, a);
                    fma2(o2[r][0], pa, vp0);
                    fma2(o2[r][1], pa, vp1);
                }
            }
            #pragma unroll
            for (int r = 0; r < 4; ++r) {
                float2 lo2 = up2(o2[r][0]), hi2 = up2(o2[r][1]);
                float o[4] = {lo2.x, lo2.y, hi2.x, hi2.y};
                size_t off = ((size_t)b * NTOK + ai0 + r) * DIM + h * 64 + d0;
                __half hh[4], hl[4];
                #pragma unroll
                for (int c = 0; c < 4; ++c) {
                    hh[c] = __float2half(o[c]);
                    hl[c] = __float2half(o[c] - __half2float(hh[c]));
                }
                *(__half2*)(g_ao_h + off)     = __halves2half2(hh[0], hh[1]);
                *(__half2*)(g_ao_h + off + 2) = __halves2half2(hh[2], hh[3]);
                *(__half2*)(g_ao_l + off)     = __halves2half2(hl[0], hl[1]);
                *(__half2*)(g_ao_l + off + 2) = __halves2half2(hl[2], hl[3]);
            }
        }
        __syncthreads();
    }
}

// ============================================================================
extern "C" void kernel_launch(void* const* d_in, const int* in_sizes, int n_in,
                              void* d_out, int out_size) {
    const float* x    = (const float*)d_in[0];
    const float* wqkv = (const float*)d_in[1];
    const float* wout = (const float*)d_in[2];
    const float* bout = (const float*)d_in[3];
    const float* Mat  = (const float*)d_in[4];
    float* y = (float*)d_out;

    static bool attr_set = false;
    if (!attr_set) {
        cudaFuncSetAttribute(gemm_kernel,
                             cudaFuncAttributeMaxDynamicSharedMemorySize, GSMEM);
        cudaFuncSetAttribute(attn_kernel,
                             cudaFuncAttributeMaxDynamicSharedMemorySize, ASMEM);
        attr_set = true;
    }

    prep_kernel<<<8192, 256>>>(x, wqkv, wout);
    gemm_kernel<<<dim3(QKDIM / 128, NROWS / 256), 256, GSMEM>>>(0, nullptr, y);
    attn_kernel<<<NB, 256, ASMEM>>>(Mat);
    gemm_kernel<<<dim3(DIM / 128, NROWS / 256), 256, GSMEM>>>(1, bout, y);
}

// round 10
// speedup vs baseline: 1.0669x; 1.0669x over previous
#include <cuda_runtime.h>
#include <cuda_fp16.h>
#include <cstdint>

// ============================================================================
// Attention_32916629357041 — fp16 2-term split GEMMs (mma.sync, sm_100 base)
//   prep:  x -> fp16 hi/lo; w_qkv (q-rows pre-scaled), w_out -> single fp16
//   gemm1: qkv = x @ w_qkv^T   (2 mma terms: Ah*B + Al*B, fp32 acc)
//   attn:  per-window softmax core (fp32, writes ao as fp16 hi/lo)
//   gemm2: y = ao @ w_out^T + b_out
// R10: back to R8 tile (CTA 128x128, warp 32x64, 2 CTA/SM); batched ldsm
//      fragment loads + two-pass mma order to break RAW stalls.
// ============================================================================

typedef unsigned long long ull;

#define NB    1024
#define NTOK  64
#define DIM   512
#define QKDIM 1536
#define NROWS (NB * NTOK)          // 65536
#define SCALE 0.125f

// ---------------- device scratch ----------------
__device__ __half g_x_h[(size_t)NROWS * DIM];
__device__ __half g_x_l[(size_t)NROWS * DIM];
__device__ __half g_w1[QKDIM * DIM];
__device__ __half g_w2[DIM * DIM];
__device__ float  g_qkv[(size_t)NROWS * QKDIM];
__device__ __half g_ao_h[(size_t)NROWS * DIM];
__device__ __half g_ao_l[(size_t)NROWS * DIM];

// ---------------- helpers ----------------
__device__ __forceinline__ ull pk2(float x, float y) {
    ull r; asm("mov.b64 %0, {%1, %2};" : "=l"(r) : "f"(x), "f"(y)); return r;
}
__device__ __forceinline__ void fma2(ull& d, ull a, ull b) {
    asm("fma.rn.f32x2 %0, %1, %2, %0;" : "+l"(d) : "l"(a), "l"(b));
}
__device__ __forceinline__ float2 up2(ull v) {
    float2 f; asm("mov.b64 {%0, %1}, %2;" : "=f"(f.x), "=f"(f.y) : "l"(v)); return f;
}
__device__ __forceinline__ uint32_t smem_u32(const void* p) {
    uint32_t a;
    asm("{ .reg .u64 t; cvta.to.shared.u64 t, %1; cvt.u32.u64 %0, t; }" : "=r"(a) : "l"(p));
    return a;
}
__device__ __forceinline__ void cpa16(uint32_t dst, const void* src) {
    asm volatile("cp.async.cg.shared.global [%0], [%1], 16;" :: "r"(dst), "l"(src));
}
__device__ __forceinline__ void cpa_commit() {
    asm volatile("cp.async.commit_group;" ::: "memory");
}
template <int N>
__device__ __forceinline__ void cpa_wait() {
    asm volatile("cp.async.wait_group %0;" :: "n"(N) : "memory");
}
__device__ __forceinline__ void ldsm4(uint32_t* r, uint32_t addr) {
    asm volatile("ldmatrix.sync.aligned.m8n8.x4.shared.b16 {%0,%1,%2,%3}, [%4];"
                 : "=r"(r[0]), "=r"(r[1]), "=r"(r[2]), "=r"(r[3]) : "r"(addr));
}
__device__ __forceinline__ void mma16816(float* c, const uint32_t* a, const uint32_t* b) {
    asm volatile(
        "mma.sync.aligned.m16n8k16.row.col.f32.f16.f16.f32 "
        "{%0,%1,%2,%3}, {%4,%5,%6,%7}, {%8,%9}, {%0,%1,%2,%3};"
        : "+f"(c[0]), "+f"(c[1]), "+f"(c[2]), "+f"(c[3])
        : "r"(a[0]), "r"(a[1]), "r"(a[2]), "r"(a[3]), "r"(b[0]), "r"(b[1]));
}

// ============================================================================
// prep
// ============================================================================
__global__ void prep_kernel(const float* __restrict__ x,
                            const float* __restrict__ w1,
                            const float* __restrict__ w2) {
    size_t stride = (size_t)gridDim.x * blockDim.x;
    size_t tid = (size_t)blockIdx.x * blockDim.x + threadIdx.x;
    for (size_t i = tid; i < (size_t)NROWS * DIM; i += stride) {
        float v = x[i];
        __half h = __float2half(v);
        g_x_h[i] = h;
        g_x_l[i] = __float2half(v - __half2float(h));
    }
    for (size_t i = tid; i < (size_t)QKDIM * DIM; i += stride) {
        float v = w1[i] * ((i < (size_t)DIM * DIM) ? SCALE : 1.0f);  // fold q-scale
        g_w1[i] = __float2half(v);
    }
    for (size_t i = tid; i < (size_t)DIM * DIM; i += stride)
        g_w2[i] = __float2half(w2[i]);
}

// ============================================================================
// gemm: C[m][n] = sum_k A[m][k]*B[n][k], K=512, A fp16 hi/lo 2-term, fp32 acc
// CTA tile 128x128, 8 warps (4M x 2N), warp tile 32x64. k-chunk 32,
// 3-stage cp.async pipeline, one __syncthreads per chunk. 2 CTAs/SM.
// ============================================================================
#define KC    32
#define ROWB  80                  // bytes per smem row (32 fp16 + 16 pad)
#define MATB  (128 * ROWB)        // 10240 per matrix
#define STG   (3 * MATB)          // Ah Al B per stage = 30720
#define GSMEM (3 * STG)           // 92160 (3 stages)

struct GemmSrc { const __half *Ah, *Al, *B; };

__device__ __forceinline__ void issue_stage(const GemmSrc& S, size_t arow0,
                                            size_t brow0, int kc, uint32_t sb,
                                            int t) {
    const __half* mats[3] = {S.Ah, S.Al, S.B};
    size_t row0s[3] = {arow0, arow0, brow0};
    #pragma unroll
    for (int m = 0; m < 3; ++m) {
        #pragma unroll
        for (int l = 0; l < 2; ++l) {
            int idx = t + l * 256;            // 0..511
            int r = idx >> 2, c16 = idx & 3;
            const __half* src =
                mats[m] + (row0s[m] + r) * DIM + kc * KC + c16 * 8;
            cpa16(sb + m * MATB + r * ROWB + c16 * 16, src);
        }
    }
    cpa_commit();
}

__global__ void __launch_bounds__(256, 2)
gemm_kernel(int which, const float* __restrict__ bias, float* __restrict__ cext) {
    extern __shared__ char sm[];
    const uint32_t sbase = smem_u32(sm);

    const int t = threadIdx.x, w = t >> 5, lane = t & 31;
    const int wm = w & 3, wn = w >> 2;
    const int nt = blockIdx.x, rt = blockIdx.y;

    GemmSrc S;
    float* C; int ldc;
    if (which == 0) { S = {g_x_h,  g_x_l,  g_w1};
                      C = g_qkv; ldc = QKDIM; }
    else            { S = {g_ao_h, g_ao_l, g_w2};
                      C = cext;  ldc = DIM; }
    const size_t arow0 = (size_t)rt * 128;
    const size_t brow0 = (size_t)nt * 128;

    float acc[2][8][4];
    #pragma unroll
    for (int mi = 0; mi < 2; ++mi)
        #pragma unroll
        for (int ni = 0; ni < 8; ++ni)
            #pragma unroll
            for (int e = 0; e < 4; ++e) acc[mi][ni][e] = 0.f;

    // ldmatrix lane addressing
    const int a_row  = wm * 32 + (lane & 15);
    const int a_koff = (lane >> 4) * 16;
    const int b_lr = lane & 7, b_g2 = lane >> 3;
    const int b_nrow_base = wn * 64 + b_lr + (b_g2 >> 1) * 8;
    const int b_koff = (b_g2 & 1) * 16;

    const int NKC = DIM / KC;   // 16
    issue_stage(S, arow0, brow0, 0, sbase, t);
    issue_stage(S, arow0, brow0, 1, sbase + STG, t);

    for (int kc = 0; kc < NKC; ++kc) {
        const uint32_t sb = sbase + (kc % 3) * STG;
        if (kc + 1 < NKC) cpa_wait<1>();   // stage kc landed; kc+1 may pend
        else              cpa_wait<0>();
        __syncthreads();                   // data visible; buf (kc+2)%3 free
        if (kc + 2 < NKC)
            issue_stage(S, arow0, brow0, kc + 2, sbase + ((kc + 2) % 3) * STG, t);

        #pragma unroll
        for (int k16 = 0; k16 < 2; ++k16) {
            const int kb = k16 * 32;      // byte offset of this k16 in the row
            // ---- batch ALL fragment loads (issue b2b, overlap latency) ----
            uint32_t ah[2][4], al[2][4], bb[4][4];
            #pragma unroll
            for (int mi = 0; mi < 2; ++mi) {
                uint32_t ad = sb + (a_row + mi * 16) * ROWB + kb + a_koff;
                ldsm4(ah[mi], ad);
                ldsm4(al[mi], ad + MATB);
            }
            #pragma unroll
            for (int g = 0; g < 4; ++g)
                ldsm4(bb[g], sb + 2 * MATB +
                              (b_nrow_base + g * 16) * ROWB + kb + b_koff);
            // ---- pass 1: all hi-term mmas (16 distinct accs) ----
            #pragma unroll
            for (int mi = 0; mi < 2; ++mi)
                #pragma unroll
                for (int g = 0; g < 4; ++g) {
                    mma16816(acc[mi][2 * g],     ah[mi], bb[g]);
                    mma16816(acc[mi][2 * g + 1], ah[mi], bb[g] + 2);
                }
            // ---- pass 2: all lo-term mmas (reuse distance = 16) ----
            #pragma unroll
            for (int mi = 0; mi < 2; ++mi)
                #pragma unroll
                for (int g = 0; g < 4; ++g) {
                    mma16816(acc[mi][2 * g],     al[mi], bb[g]);
                    mma16816(acc[mi][2 * g + 1], al[mi], bb[g] + 2);
                }
        }
    }

    // ---- epilogue: direct register -> gmem stores ----
    const int qr = lane >> 2, qc = lane & 3;
    #pragma unroll
    for (int mi = 0; mi < 2; ++mi) {
        #pragma unroll
        for (int ni = 0; ni < 8; ++ni) {
            size_t row = arow0 + wm * 32 + mi * 16 + qr;
            int col = nt * 128 + wn * 64 + ni * 8 + qc * 2;
            float2 v0 = make_float2(acc[mi][ni][0], acc[mi][ni][1]);
            float2 v1 = make_float2(acc[mi][ni][2], acc[mi][ni][3]);
            if (bias != nullptr) {
                float2 bz = *(const float2*)(bias + col);
                v0.x += bz.x; v0.y += bz.y; v1.x += bz.x; v1.y += bz.y;
            }
            *(float2*)(C + row * ldc + col)       = v0;
            *(float2*)(C + (row + 8) * ldc + col) = v1;
        }
    }
}

// ============================================================================
// attention core: per window, fp32. Reads g_qkv, writes g_ao_{h,l} (fp16).
// ============================================================================
#define AQ 68
#define ASMEM ((4 * 64 * AQ + 240) * 4)

__global__ void __launch_bounds__(256, 2)
attn_kernel(const float* __restrict__ Mat) {
    extern __shared__ float smf[];
    float* qs   = smf;
    float* ks   = qs + 64 * AQ;
    float* vs   = ks + 64 * AQ;
    float* as_  = vs + 64 * AQ;
    float* mats = as_ + 64 * AQ;

    const int b = blockIdx.x, t = threadIdx.x;
    if (t < 225) mats[t] = Mat[t];

    const int tx = t & 15, ty = t >> 4;
    const int ai0 = ty * 4, tj = tx, d0 = tx * 4;
    const float* qg = g_qkv + (size_t)b * NTOK * QKDIM;

    for (int h = 0; h < 8; ++h) {
        #pragma unroll
        for (int l = 0; l < 4; ++l) {
            int idx = t + l * 256;           // 0..1023
            int row = idx >> 4, c4 = idx & 15;
            const float* rp = qg + (size_t)row * QKDIM + h * 64 + c4 * 4;
            *(float4*)(qs + row * AQ + c4 * 4) = *(const float4*)(rp);
            *(float4*)(ks + row * AQ + c4 * 4) = *(const float4*)(rp + 512);
            *(float4*)(vs + row * AQ + c4 * 4) = *(const float4*)(rp + 1024);
        }
        __syncthreads();

        // ---- sim = q k^T + bias; softmax ----
        {
            ull s2[4][4];
            #pragma unroll
            for (int r = 0; r < 4; ++r)
                #pragma unroll
                for (int c = 0; c < 4; ++c) s2[r][c] = 0ULL;

            #pragma unroll 4
            for (int dq = 0; dq < 16; ++dq) {
                float4 qv[4], kv[4];
                #pragma unroll
                for (int r = 0; r < 4; ++r)
                    qv[r] = *(const float4*)(qs + (ai0 + r) * AQ + 4 * dq);
                #pragma unroll
                for (int c = 0; c < 4; ++c)
                    kv[c] = *(const float4*)(ks + (tj + 16 * c) * AQ + 4 * dq);
                #pragma unroll
                for (int r = 0; r < 4; ++r) {
                    ull q01 = pk2(qv[r].x, qv[r].y), q23 = pk2(qv[r].z, qv[r].w);
                    #pragma unroll
                    for (int c = 0; c < 4; ++c) {
                        fma2(s2[r][c], q01, pk2(kv[c].x, kv[c].y));
                        fma2(s2[r][c], q23, pk2(kv[c].z, kv[c].w));
                    }
                }
            }
            #pragma unroll
            for (int r = 0; r < 4; ++r) {
                int i = ai0 + r;
                int r1 = i >> 3, c1 = i & 7;
                float sim[4];
                #pragma unroll
                for (int c = 0; c < 4; ++c) {
                    int j = tj + 16 * c;
                    int r2 = j >> 3, c2 = j & 7;
                    float2 p = up2(s2[r][c]);
                    sim[c] = p.x + p.y + mats[(r2 - r1 + 7) * 15 + (c2 - c1 + 7)];
                }
                float m = fmaxf(fmaxf(sim[0], sim[1]), fmaxf(sim[2], sim[3]));
                m = fmaxf(m, __shfl_xor_sync(0xffffffffu, m, 1));
                m = fmaxf(m, __shfl_xor_sync(0xffffffffu, m, 2));
                m = fmaxf(m, __shfl_xor_sync(0xffffffffu, m, 4));
                m = fmaxf(m, __shfl_xor_sync(0xffffffffu, m, 8));
                float e0 = __expf(sim[0] - m), e1 = __expf(sim[1] - m);
                float e2 = __expf(sim[2] - m), e3 = __expf(sim[3] - m);
                float s = e0 + e1 + e2 + e3;
                s += __shfl_xor_sync(0xffffffffu, s, 1);
                s += __shfl_xor_sync(0xffffffffu, s, 2);
                s += __shfl_xor_sync(0xffffffffu, s, 4);
                s += __shfl_xor_sync(0xffffffffu, s, 8);
                float inv = 1.f / s;
                as_[(ai0 + r) * AQ + tj]      = e0 * inv;
                as_[(ai0 + r) * AQ + tj + 16] = e1 * inv;
                as_[(ai0 + r) * AQ + tj + 32] = e2 * inv;
                as_[(ai0 + r) * AQ + tj + 48] = e3 * inv;
            }
        }
        __syncthreads();

        // ---- out = attn @ v ; split to fp16 hi/lo ----
        {
            ull o2[4][2];
            #pragma unroll
            for (int r = 0; r < 4; ++r) { o2[r][0] = 0ULL; o2[r][1] = 0ULL; }
            #pragma unroll 4
            for (int j = 0; j < 64; ++j) {
                float4 vv = *(const float4*)(vs + j * AQ + d0);
                ull vp0 = pk2(vv.x, vv.y), vp1 = pk2(vv.z, vv.w);
                #pragma unroll
                for (int r = 0; r < 4; ++r) {
                    float a = as_[(ai0 + r) * AQ + j];
                    ull pa = pk2(a, a);
                    fma2(o2[r][0], pa, vp0);
                    fma2(o2[r][1], pa, vp1);
                }
            }
            #pragma unroll
            for (int r = 0; r < 4; ++r) {
                float2 lo2 = up2(o2[r][0]), hi2 = up2(o2[r][1]);
                float o[4] = {lo2.x, lo2.y, hi2.x, hi2.y};
                size_t off = ((size_t)b * NTOK + ai0 + r) * DIM + h * 64 + d0;
                __half hh[4], hl[4];
                #pragma unroll
                for (int c = 0; c < 4; ++c) {
                    hh[c] = __float2half(o[c]);
                    hl[c] = __float2half(o[c] - __half2float(hh[c]));
                }
                *(__half2*)(g_ao_h + off)     = __halves2half2(hh[0], hh[1]);
                *(__half2*)(g_ao_h + off + 2) = __halves2half2(hh[2], hh[3]);
                *(__half2*)(g_ao_l + off)     = __halves2half2(hl[0], hl[1]);
                *(__half2*)(g_ao_l + off + 2) = __halves2half2(hl[2], hl[3]);
            }
        }
        __syncthreads();
    }
}

// ============================================================================
extern "C" void kernel_launch(void* const* d_in, const int* in_sizes, int n_in,
                              void* d_out, int out_size) {
    const float* x    = (const float*)d_in[0];
    const float* wqkv = (const float*)d_in[1];
    const float* wout = (const float*)d_in[2];
    const float* bout = (const float*)d_in[3];
    const float* Mat  = (const float*)d_in[4];
    float* y = (float*)d_out;

    static bool attr_set = false;
    if (!attr_set) {
        cudaFuncSetAttribute(gemm_kernel,
                             cudaFuncAttributeMaxDynamicSharedMemorySize, GSMEM);
        cudaFuncSetAttribute(attn_kernel,
                             cudaFuncAttributeMaxDynamicSharedMemorySize, ASMEM);
        attr_set = true;
    }

    prep_kernel<<<8192, 256>>>(x, wqkv, wout);
    gemm_kernel<<<dim3(QKDIM / 128, NROWS / 128), 256, GSMEM>>>(0, nullptr, y);
    attn_kernel<<<NB, 256, ASMEM>>>(Mat);
    gemm_kernel<<<dim3(DIM / 128, NROWS / 128), 256, GSMEM>>>(1, bout, y);
}

// round 11
// speedup vs baseline: 1.1645x; 1.0914x over previous
#include <cuda_runtime.h>
#include <cuda_fp16.h>
#include <cstdint>

// ============================================================================
// Attention_32916629357041 — fp16 2-term split GEMMs (mma.sync, sm_100 base)
//   prep:  x -> fp16 hi/lo; w_qkv (q-rows pre-scaled), w_out -> single fp16
//   gemm1: qkv = x @ w_qkv^T   (2 mma terms: Ah*B + Al*B, fp32 acc)
//   attn:  per-window softmax core (fp32, writes ao as fp16 hi/lo)
//   gemm2: y = ao @ w_out^T + b_out
// R11: KC=64 k-chunks (8 instead of 16) + 2-stage pipeline — halves
//      chunk-boundary drain; tensor pipe confirmed 2048 MAC/cyc/SM.
// ============================================================================

typedef unsigned long long ull;

#define NB    1024
#define NTOK  64
#define DIM   512
#define QKDIM 1536
#define NROWS (NB * NTOK)          // 65536
#define SCALE 0.125f

// ---------------- device scratch ----------------
__device__ __half g_x_h[(size_t)NROWS * DIM];
__device__ __half g_x_l[(size_t)NROWS * DIM];
__device__ __half g_w1[QKDIM * DIM];
__device__ __half g_w2[DIM * DIM];
__device__ float  g_qkv[(size_t)NROWS * QKDIM];
__device__ __half g_ao_h[(size_t)NROWS * DIM];
__device__ __half g_ao_l[(size_t)NROWS * DIM];

// ---------------- helpers ----------------
__device__ __forceinline__ ull pk2(float x, float y) {
    ull r; asm("mov.b64 %0, {%1, %2};" : "=l"(r) : "f"(x), "f"(y)); return r;
}
__device__ __forceinline__ void fma2(ull& d, ull a, ull b) {
    asm("fma.rn.f32x2 %0, %1, %2, %0;" : "+l"(d) : "l"(a), "l"(b));
}
__device__ __forceinline__ float2 up2(ull v) {
    float2 f; asm("mov.b64 {%0, %1}, %2;" : "=f"(f.x), "=f"(f.y) : "l"(v)); return f;
}
__device__ __forceinline__ uint32_t smem_u32(const void* p) {
    uint32_t a;
    asm("{ .reg .u64 t; cvta.to.shared.u64 t, %1; cvt.u32.u64 %0, t; }" : "=r"(a) : "l"(p));
    return a;
}
__device__ __forceinline__ void cpa16(uint32_t dst, const void* src) {
    asm volatile("cp.async.cg.shared.global [%0], [%1], 16;" :: "r"(dst), "l"(src));
}
__device__ __forceinline__ void cpa_commit() {
    asm volatile("cp.async.commit_group;" ::: "memory");
}
template <int N>
__device__ __forceinline__ void cpa_wait() {
    asm volatile("cp.async.wait_group %0;" :: "n"(N) : "memory");
}
__device__ __forceinline__ void ldsm4(uint32_t* r, uint32_t addr) {
    asm volatile("ldmatrix.sync.aligned.m8n8.x4.shared.b16 {%0,%1,%2,%3}, [%4];"
                 : "=r"(r[0]), "=r"(r[1]), "=r"(r[2]), "=r"(r[3]) : "r"(addr));
}
__device__ __forceinline__ void mma16816(float* c, const uint32_t* a, const uint32_t* b) {
    asm volatile(
        "mma.sync.aligned.m16n8k16.row.col.f32.f16.f16.f32 "
        "{%0,%1,%2,%3}, {%4,%5,%6,%7}, {%8,%9}, {%0,%1,%2,%3};"
        : "+f"(c[0]), "+f"(c[1]), "+f"(c[2]), "+f"(c[3])
        : "r"(a[0]), "r"(a[1]), "r"(a[2]), "r"(a[3]), "r"(b[0]), "r"(b[1]));
}

// ============================================================================
// prep
// ============================================================================
__global__ void prep_kernel(const float* __restrict__ x,
                            const float* __restrict__ w1,
                            const float* __restrict__ w2) {
    size_t stride = (size_t)gridDim.x * blockDim.x;
    size_t tid = (size_t)blockIdx.x * blockDim.x + threadIdx.x;
    for (size_t i = tid; i < (size_t)NROWS * DIM; i += stride) {
        float v = x[i];
        __half h = __float2half(v);
        g_x_h[i] = h;
        g_x_l[i] = __float2half(v - __half2float(h));
    }
    for (size_t i = tid; i < (size_t)QKDIM * DIM; i += stride) {
        float v = w1[i] * ((i < (size_t)DIM * DIM) ? SCALE : 1.0f);  // fold q-scale
        g_w1[i] = __float2half(v);
    }
    for (size_t i = tid; i < (size_t)DIM * DIM; i += stride)
        g_w2[i] = __float2half(w2[i]);
}

// ============================================================================
// gemm: C[m][n] = sum_k A[m][k]*B[n][k], K=512, A fp16 hi/lo 2-term, fp32 acc
// CTA tile 128x128, 8 warps (4M x 2N), warp tile 32x64. k-chunk 64,
// 2-stage cp.async pipeline, one __syncthreads per chunk. 2 CTAs/SM.
// ============================================================================
#define KC    64
#define ROWB  144                 // bytes per smem row (64 fp16 + 16 pad)
#define MATB  (128 * ROWB)        // 18432 per matrix
#define STG   (3 * MATB)          // Ah Al B per stage = 55296
#define GSMEM (2 * STG)           // 110592 (2 stages)

struct GemmSrc { const __half *Ah, *Al, *B; };

__device__ __forceinline__ void issue_stage(const GemmSrc& S, size_t arow0,
                                            size_t brow0, int kc, uint32_t sb,
                                            int t) {
    const __half* mats[3] = {S.Ah, S.Al, S.B};
    size_t row0s[3] = {arow0, arow0, brow0};
    #pragma unroll
    for (int m = 0; m < 3; ++m) {
        #pragma unroll
        for (int l = 0; l < 4; ++l) {
            int idx = t + l * 256;            // 0..1023 (128 rows x 8 c16)
            int r = idx >> 3, c16 = idx & 7;
            const __half* src =
                mats[m] + (row0s[m] + r) * DIM + kc * KC + c16 * 8;
            cpa16(sb + m * MATB + r * ROWB + c16 * 16, src);
        }
    }
    cpa_commit();
}

__global__ void __launch_bounds__(256, 2)
gemm_kernel(int which, const float* __restrict__ bias, float* __restrict__ cext) {
    extern __shared__ char sm[];
    const uint32_t sbase = smem_u32(sm);

    const int t = threadIdx.x, w = t >> 5, lane = t & 31;
    const int wm = w & 3, wn = w >> 2;
    const int nt = blockIdx.x, rt = blockIdx.y;

    GemmSrc S;
    float* C; int ldc;
    if (which == 0) { S = {g_x_h,  g_x_l,  g_w1};
                      C = g_qkv; ldc = QKDIM; }
    else            { S = {g_ao_h, g_ao_l, g_w2};
                      C = cext;  ldc = DIM; }
    const size_t arow0 = (size_t)rt * 128;
    const size_t brow0 = (size_t)nt * 128;

    float acc[2][8][4];
    #pragma unroll
    for (int mi = 0; mi < 2; ++mi)
        #pragma unroll
        for (int ni = 0; ni < 8; ++ni)
            #pragma unroll
            for (int e = 0; e < 4; ++e) acc[mi][ni][e] = 0.f;

    // ldmatrix lane addressing
    const int a_row  = wm * 32 + (lane & 15);
    const int a_koff = (lane >> 4) * 16;
    const int b_lr = lane & 7, b_g2 = lane >> 3;
    const int b_nrow_base = wn * 64 + b_lr + (b_g2 >> 1) * 8;
    const int b_koff = (b_g2 & 1) * 16;

    const int NKC = DIM / KC;   // 8
    issue_stage(S, arow0, brow0, 0, sbase, t);

    for (int kc = 0; kc < NKC; ++kc) {
        const uint32_t sb = sbase + (kc & 1) * STG;
        cpa_wait<0>();              // chunk kc landed (issued >=1 chunk ago)
        __syncthreads();            // visible to all; buf^1 fully consumed
        if (kc + 1 < NKC)
            issue_stage(S, arow0, brow0, kc + 1, sbase + ((kc + 1) & 1) * STG, t);

        #pragma unroll
        for (int k16 = 0; k16 < 4; ++k16) {
            const int kb = k16 * 32;      // byte offset of this k16 in the row
            uint32_t ah[2][4], al[2][4], bb[4][4];
            #pragma unroll
            for (int mi = 0; mi < 2; ++mi) {
                uint32_t ad = sb + (a_row + mi * 16) * ROWB + kb + a_koff;
                ldsm4(ah[mi], ad);
                ldsm4(al[mi], ad + MATB);
            }
            #pragma unroll
            for (int g = 0; g < 4; ++g)
                ldsm4(bb[g], sb + 2 * MATB +
                              (b_nrow_base + g * 16) * ROWB + kb + b_koff);
            #pragma unroll
            for (int mi = 0; mi < 2; ++mi)
                #pragma unroll
                for (int g = 0; g < 4; ++g) {
                    mma16816(acc[mi][2 * g],     ah[mi], bb[g]);
                    mma16816(acc[mi][2 * g + 1], ah[mi], bb[g] + 2);
                }
            #pragma unroll
            for (int mi = 0; mi < 2; ++mi)
                #pragma unroll
                for (int g = 0; g < 4; ++g) {
                    mma16816(acc[mi][2 * g],     al[mi], bb[g]);
                    mma16816(acc[mi][2 * g + 1], al[mi], bb[g] + 2);
                }
        }
    }

    // ---- epilogue: direct register -> gmem stores ----
    const int qr = lane >> 2, qc = lane & 3;
    #pragma unroll
    for (int mi = 0; mi < 2; ++mi) {
        #pragma unroll
        for (int ni = 0; ni < 8; ++ni) {
            size_t row = arow0 + wm * 32 + mi * 16 + qr;
            int col = nt * 128 + wn * 64 + ni * 8 + qc * 2;
            float2 v0 = make_float2(acc[mi][ni][0], acc[mi][ni][1]);
            float2 v1 = make_float2(acc[mi][ni][2], acc[mi][ni][3]);
            if (bias != nullptr) {
                float2 bz = *(const float2*)(bias + col);
                v0.x += bz.x; v0.y += bz.y; v1.x += bz.x; v1.y += bz.y;
            }
            *(float2*)(C + row * ldc + col)       = v0;
            *(float2*)(C + (row + 8) * ldc + col) = v1;
        }
    }
}

// ============================================================================
// attention core: per window, fp32. Reads g_qkv, writes g_ao_{h,l} (fp16).
// ============================================================================
#define AQ 68
#define ASMEM ((4 * 64 * AQ + 240) * 4)

__global__ void __launch_bounds__(256, 2)
attn_kernel(const float* __restrict__ Mat) {
    extern __shared__ float smf[];
    float* qs   = smf;
    float* ks   = qs + 64 * AQ;
    float* vs   = ks + 64 * AQ;
    float* as_  = vs + 64 * AQ;
    float* mats = as_ + 64 * AQ;

    const int b = blockIdx.x, t = threadIdx.x;
    if (t < 225) mats[t] = Mat[t];

    const int tx = t & 15, ty = t >> 4;
    const int ai0 = ty * 4, tj = tx, d0 = tx * 4;
    const float* qg = g_qkv + (size_t)b * NTOK * QKDIM;

    for (int h = 0; h < 8; ++h) {
        #pragma unroll
        for (int l = 0; l < 4; ++l) {
            int idx = t + l * 256;           // 0..1023
            int row = idx >> 4, c4 = idx & 15;
            const float* rp = qg + (size_t)row * QKDIM + h * 64 + c4 * 4;
            *(float4*)(qs + row * AQ + c4 * 4) = *(const float4*)(rp);
            *(float4*)(ks + row * AQ + c4 * 4) = *(const float4*)(rp + 512);
            *(float4*)(vs + row * AQ + c4 * 4) = *(const float4*)(rp + 1024);
        }
        __syncthreads();

        // ---- sim = q k^T + bias; softmax ----
        {
            ull s2[4][4];
            #pragma unroll
            for (int r = 0; r < 4; ++r)
                #pragma unroll
                for (int c = 0; c < 4; ++c) s2[r][c] = 0ULL;

            #pragma unroll 4
            for (int dq = 0; dq < 16; ++dq) {
                float4 qv[4], kv[4];
                #pragma unroll
                for (int r = 0; r < 4; ++r)
                    qv[r] = *(const float4*)(qs + (ai0 + r) * AQ + 4 * dq);
                #pragma unroll
                for (int c = 0; c < 4; ++c)
                    kv[c] = *(const float4*)(ks + (tj + 16 * c) * AQ + 4 * dq);
                #pragma unroll
                for (int r = 0; r < 4; ++r) {
                    ull q01 = pk2(qv[r].x, qv[r].y), q23 = pk2(qv[r].z, qv[r].w);
                    #pragma unroll
                    for (int c = 0; c < 4; ++c) {
                        fma2(s2[r][c], q01, pk2(kv[c].x, kv[c].y));
                        fma2(s2[r][c], q23, pk2(kv[c].z, kv[c].w));
                    }
                }
            }
            #pragma unroll
            for (int r = 0; r < 4; ++r) {
                int i = ai0 + r;
                int r1 = i >> 3, c1 = i & 7;
                float sim[4];
                #pragma unroll
                for (int c = 0; c < 4; ++c) {
                    int j = tj + 16 * c;
                    int r2 = j >> 3, c2 = j & 7;
                    float2 p = up2(s2[r][c]);
                    sim[c] = p.x + p.y + mats[(r2 - r1 + 7) * 15 + (c2 - c1 + 7)];
                }
                float m = fmaxf(fmaxf(sim[0], sim[1]), fmaxf(sim[2], sim[3]));
                m = fmaxf(m, __shfl_xor_sync(0xffffffffu, m, 1));
                m = fmaxf(m, __shfl_xor_sync(0xffffffffu, m, 2));
                m = fmaxf(m, __shfl_xor_sync(0xffffffffu, m, 4));
                m = fmaxf(m, __shfl_xor_sync(0xffffffffu, m, 8));
                float e0 = __expf(sim[0] - m), e1 = __expf(sim[1] - m);
                float e2 = __expf(sim[2] - m), e3 = __expf(sim[3] - m);
                float s = e0 + e1 + e2 + e3;
                s += __shfl_xor_sync(0xffffffffu, s, 1);
                s += __shfl_xor_sync(0xffffffffu, s, 2);
                s += __shfl_xor_sync(0xffffffffu, s, 4);
                s += __shfl_xor_sync(0xffffffffu, s, 8);
                float inv = 1.f / s;
                as_[(ai0 + r) * AQ + tj]      = e0 * inv;
                as_[(ai0 + r) * AQ + tj + 16] = e1 * inv;
                as_[(ai0 + r) * AQ + tj + 32] = e2 * inv;
                as_[(ai0 + r) * AQ + tj + 48] = e3 * inv;
            }
        }
        __syncthreads();

        // ---- out = attn @ v ; split to fp16 hi/lo ----
        {
            ull o2[4][2];
            #pragma unroll
            for (int r = 0; r < 4; ++r) { o2[r][0] = 0ULL; o2[r][1] = 0ULL; }
            #pragma unroll 4
            for (int j = 0; j < 64; ++j) {
                float4 vv = *(const float4*)(vs + j * AQ + d0);
                ull vp0 = pk2(vv.x, vv.y), vp1 = pk2(vv.z, vv.w);
                #pragma unroll
                for (int r = 0; r < 4; ++r) {
                    float a = as_[(ai0 + r) * AQ + j];
                    ull pa = pk2(a, a);
                    fma2(o2[r][0], pa, vp0);
                    fma2(o2[r][1], pa, vp1);
                }
            }
            #pragma unroll
            for (int r = 0; r < 4; ++r) {
                float2 lo2 = up2(o2[r][0]), hi2 = up2(o2[r][1]);
                float o[4] = {lo2.x, lo2.y, hi2.x, hi2.y};
                size_t off = ((size_t)b * NTOK + ai0 + r) * DIM + h * 64 + d0;
                __half hh[4], hl[4];
                #pragma unroll
                for (int c = 0; c < 4; ++c) {
                    hh[c] = __float2half(o[c]);
                    hl[c] = __float2half(o[c] - __half2float(hh[c]));
                }
                *(__half2*)(g_ao_h + off)     = __halves2half2(hh[0], hh[1]);
                *(__half2*)(g_ao_h + off + 2) = __halves2half2(hh[2], hh[3]);
                *(__half2*)(g_ao_l + off)     = __halves2half2(hl[0], hl[1]);
                *(__half2*)(g_ao_l + off + 2) = __halves2half2(hl[2], hl[3]);
            }
        }
        __syncthreads();
    }
}

// ============================================================================
extern "C" void kernel_launch(void* const* d_in, const int* in_sizes, int n_in,
                              void* d_out, int out_size) {
    const float* x    = (const float*)d_in[0];
    const float* wqkv = (const float*)d_in[1];
    const float* wout = (const float*)d_in[2];
    const float* bout = (const float*)d_in[3];
    const float* Mat  = (const float*)d_in[4];
    float* y = (float*)d_out;

    static bool attr_set = false;
    if (!attr_set) {
        cudaFuncSetAttribute(gemm_kernel,
                             cudaFuncAttributeMaxDynamicSharedMemorySize, GSMEM);
        cudaFuncSetAttribute(attn_kernel,
                             cudaFuncAttributeMaxDynamicSharedMemorySize, ASMEM);
        attr_set = true;
    }

    prep_kernel<<<8192, 256>>>(x, wqkv, wout);
    gemm_kernel<<<dim3(QKDIM / 128, NROWS / 128), 256, GSMEM>>>(0, nullptr, y);
    attn_kernel<<<NB, 256, ASMEM>>>(Mat);
    gemm_kernel<<<dim3(DIM / 128, NROWS / 128), 256, GSMEM>>>(1, bout, y);
}

// round 12
// speedup vs baseline: 1.6174x; 1.3890x over previous
#include <cuda_runtime.h>
#include <cuda_fp16.h>
#include <cstdint>

// ============================================================================
// Attention_32916629357041 — single-fp16 GEMMs (mma.sync, sm_100 base)
//   prep:  x -> fp16; w_qkv (q-rows pre-scaled), w_out -> fp16
//   gemm1: qkv = x @ w_qkv^T   (1 mma term, fp32 acc)
//   attn:  per-window softmax core (fp32, writes ao as fp16)
//   gemm2: y = ao @ w_out^T + b_out
// R12: all lo terms dropped (error budget: 2 extra fp16 sources ~ sqrt(2)x
//      current 2.42e-4 << 1e-3). GEMM MACs halve; KC=64 + 3-stage pipeline.
// ============================================================================

typedef unsigned long long ull;

#define NB    1024
#define NTOK  64
#define DIM   512
#define QKDIM 1536
#define NROWS (NB * NTOK)          // 65536
#define SCALE 0.125f

// ---------------- device scratch ----------------
__device__ __half g_x_h[(size_t)NROWS * DIM];
__device__ __half g_w1[QKDIM * DIM];
__device__ __half g_w2[DIM * DIM];
__device__ float  g_qkv[(size_t)NROWS * QKDIM];
__device__ __half g_ao_h[(size_t)NROWS * DIM];

// ---------------- helpers ----------------
__device__ __forceinline__ ull pk2(float x, float y) {
    ull r; asm("mov.b64 %0, {%1, %2};" : "=l"(r) : "f"(x), "f"(y)); return r;
}
__device__ __forceinline__ void fma2(ull& d, ull a, ull b) {
    asm("fma.rn.f32x2 %0, %1, %2, %0;" : "+l"(d) : "l"(a), "l"(b));
}
__device__ __forceinline__ float2 up2(ull v) {
    float2 f; asm("mov.b64 {%0, %1}, %2;" : "=f"(f.x), "=f"(f.y) : "l"(v)); return f;
}
__device__ __forceinline__ uint32_t smem_u32(const void* p) {
    uint32_t a;
    asm("{ .reg .u64 t; cvta.to.shared.u64 t, %1; cvt.u32.u64 %0, t; }" : "=r"(a) : "l"(p));
    return a;
}
__device__ __forceinline__ void cpa16(uint32_t dst, const void* src) {
    asm volatile("cp.async.cg.shared.global [%0], [%1], 16;" :: "r"(dst), "l"(src));
}
__device__ __forceinline__ void cpa_commit() {
    asm volatile("cp.async.commit_group;" ::: "memory");
}
template <int N>
__device__ __forceinline__ void cpa_wait() {
    asm volatile("cp.async.wait_group %0;" :: "n"(N) : "memory");
}
__device__ __forceinline__ void ldsm4(uint32_t* r, uint32_t addr) {
    asm volatile("ldmatrix.sync.aligned.m8n8.x4.shared.b16 {%0,%1,%2,%3}, [%4];"
                 : "=r"(r[0]), "=r"(r[1]), "=r"(r[2]), "=r"(r[3]) : "r"(addr));
}
__device__ __forceinline__ void mma16816(float* c, const uint32_t* a, const uint32_t* b) {
    asm volatile(
        "mma.sync.aligned.m16n8k16.row.col.f32.f16.f16.f32 "
        "{%0,%1,%2,%3}, {%4,%5,%6,%7}, {%8,%9}, {%0,%1,%2,%3};"
        : "+f"(c[0]), "+f"(c[1]), "+f"(c[2]), "+f"(c[3])
        : "r"(a[0]), "r"(a[1]), "r"(a[2]), "r"(a[3]), "r"(b[0]), "r"(b[1]));
}

// ============================================================================
// prep
// ============================================================================
__global__ void prep_kernel(const float* __restrict__ x,
                            const float* __restrict__ w1,
                            const float* __restrict__ w2) {
    size_t stride = (size_t)gridDim.x * blockDim.x;
    size_t tid = (size_t)blockIdx.x * blockDim.x + threadIdx.x;
    for (size_t i = tid; i < (size_t)NROWS * DIM; i += stride)
        g_x_h[i] = __float2half(x[i]);
    for (size_t i = tid; i < (size_t)QKDIM * DIM; i += stride) {
        float v = w1[i] * ((i < (size_t)DIM * DIM) ? SCALE : 1.0f);  // fold q-scale
        g_w1[i] = __float2half(v);
    }
    for (size_t i = tid; i < (size_t)DIM * DIM; i += stride)
        g_w2[i] = __float2half(w2[i]);
}

// ============================================================================
// gemm: C[m][n] = sum_k A[m][k]*B[n][k], K=512, fp16 single, fp32 acc
// CTA tile 128x128, 8 warps (4M x 2N), warp tile 32x64. k-chunk 64,
// 3-stage cp.async pipeline, one __syncthreads per chunk. 2 CTAs/SM.
// ============================================================================
#define KC    64
#define ROWB  144                 // bytes per smem row (64 fp16 + 16 pad)
#define MATB  (128 * ROWB)        // 18432 per matrix
#define STG   (2 * MATB)          // A B per stage = 36864
#define GSMEM (3 * STG)           // 110592 (3 stages)

struct GemmSrc { const __half *A, *B; };

__device__ __forceinline__ void issue_stage(const GemmSrc& S, size_t arow0,
                                            size_t brow0, int kc, uint32_t sb,
                                            int t) {
    const __half* mats[2] = {S.A, S.B};
    size_t row0s[2] = {arow0, brow0};
    #pragma unroll
    for (int m = 0; m < 2; ++m) {
        #pragma unroll
        for (int l = 0; l < 4; ++l) {
            int idx = t + l * 256;            // 0..1023 (128 rows x 8 c16)
            int r = idx >> 3, c16 = idx & 7;
            const __half* src =
                mats[m] + (row0s[m] + r) * DIM + kc * KC + c16 * 8;
            cpa16(sb + m * MATB + r * ROWB + c16 * 16, src);
        }
    }
    cpa_commit();
}

__global__ void __launch_bounds__(256, 2)
gemm_kernel(int which, const float* __restrict__ bias, float* __restrict__ cext) {
    extern __shared__ char sm[];
    const uint32_t sbase = smem_u32(sm);

    const int t = threadIdx.x, w = t >> 5, lane = t & 31;
    const int wm = w & 3, wn = w >> 2;
    const int nt = blockIdx.x, rt = blockIdx.y;

    GemmSrc S;
    float* C; int ldc;
    if (which == 0) { S = {g_x_h,  g_w1}; C = g_qkv; ldc = QKDIM; }
    else            { S = {g_ao_h, g_w2}; C = cext;  ldc = DIM; }
    const size_t arow0 = (size_t)rt * 128;
    const size_t brow0 = (size_t)nt * 128;

    float acc[2][8][4];
    #pragma unroll
    for (int mi = 0; mi < 2; ++mi)
        #pragma unroll
        for (int ni = 0; ni < 8; ++ni)
            #pragma unroll
            for (int e = 0; e < 4; ++e) acc[mi][ni][e] = 0.f;

    // ldmatrix lane addressing
    const int a_row  = wm * 32 + (lane & 15);
    const int a_koff = (lane >> 4) * 16;
    const int b_lr = lane & 7, b_g2 = lane >> 3;
    const int b_nrow_base = wn * 64 + b_lr + (b_g2 >> 1) * 8;
    const int b_koff = (b_g2 & 1) * 16;

    const int NKC = DIM / KC;   // 8
    issue_stage(S, arow0, brow0, 0, sbase, t);
    issue_stage(S, arow0, brow0, 1, sbase + STG, t);

    for (int kc = 0; kc < NKC; ++kc) {
        const uint32_t sb = sbase + (kc % 3) * STG;
        if (kc + 1 < NKC) cpa_wait<1>();   // stage kc landed; kc+1 may pend
        else              cpa_wait<0>();
        __syncthreads();                   // data visible; buf (kc+2)%3 free
        if (kc + 2 < NKC)
            issue_stage(S, arow0, brow0, kc + 2, sbase + ((kc + 2) % 3) * STG, t);

        #pragma unroll
        for (int k16 = 0; k16 < 4; ++k16) {
            const int kb = k16 * 32;      // byte offset of this k16 in the row
            uint32_t ah[2][4], bb[4][4];
            #pragma unroll
            for (int mi = 0; mi < 2; ++mi)
                ldsm4(ah[mi], sb + (a_row + mi * 16) * ROWB + kb + a_koff);
            #pragma unroll
            for (int g = 0; g < 4; ++g)
                ldsm4(bb[g], sb + MATB +
                              (b_nrow_base + g * 16) * ROWB + kb + b_koff);
            #pragma unroll
            for (int mi = 0; mi < 2; ++mi)
                #pragma unroll
                for (int g = 0; g < 4; ++g) {
                    mma16816(acc[mi][2 * g],     ah[mi], bb[g]);
                    mma16816(acc[mi][2 * g + 1], ah[mi], bb[g] + 2);
                }
        }
    }

    // ---- epilogue: direct register -> gmem stores ----
    const int qr = lane >> 2, qc = lane & 3;
    #pragma unroll
    for (int mi = 0; mi < 2; ++mi) {
        #pragma unroll
        for (int ni = 0; ni < 8; ++ni) {
            size_t row = arow0 + wm * 32 + mi * 16 + qr;
            int col = nt * 128 + wn * 64 + ni * 8 + qc * 2;
            float2 v0 = make_float2(acc[mi][ni][0], acc[mi][ni][1]);
            float2 v1 = make_float2(acc[mi][ni][2], acc[mi][ni][3]);
            if (bias != nullptr) {
                float2 bz = *(const float2*)(bias + col);
                v0.x += bz.x; v0.y += bz.y; v1.x += bz.x; v1.y += bz.y;
            }
            *(float2*)(C + row * ldc + col)       = v0;
            *(float2*)(C + (row + 8) * ldc + col) = v1;
        }
    }
}

// ============================================================================
// attention core: per window, fp32. Reads g_qkv, writes g_ao_h (fp16).
// ============================================================================
#define AQ 68
#define ASMEM ((4 * 64 * AQ + 240) * 4)

__global__ void __launch_bounds__(256, 2)
attn_kernel(const float* __restrict__ Mat) {
    extern __shared__ float smf[];
    float* qs   = smf;
    float* ks   = qs + 64 * AQ;
    float* vs   = ks + 64 * AQ;
    float* as_  = vs + 64 * AQ;
    float* mats = as_ + 64 * AQ;

    const int b = blockIdx.x, t = threadIdx.x;
    if (t < 225) mats[t] = Mat[t];

    const int tx = t & 15, ty = t >> 4;
    const int ai0 = ty * 4, tj = tx, d0 = tx * 4;
    const float* qg = g_qkv + (size_t)b * NTOK * QKDIM;

    for (int h = 0; h < 8; ++h) {
        #pragma unroll
        for (int l = 0; l < 4; ++l) {
            int idx = t + l * 256;           // 0..1023
            int row = idx >> 4, c4 = idx & 15;
            const float* rp = qg + (size_t)row * QKDIM + h * 64 + c4 * 4;
            *(float4*)(qs + row * AQ + c4 * 4) = *(const float4*)(rp);
            *(float4*)(ks + row * AQ + c4 * 4) = *(const float4*)(rp + 512);
            *(float4*)(vs + row * AQ + c4 * 4) = *(const float4*)(rp + 1024);
        }
        __syncthreads();

        // ---- sim = q k^T + bias; softmax ----
        {
            ull s2[4][4];
            #pragma unroll
            for (int r = 0; r < 4; ++r)
                #pragma unroll
                for (int c = 0; c < 4; ++c) s2[r][c] = 0ULL;

            #pragma unroll 4
            for (int dq = 0; dq < 16; ++dq) {
                float4 qv[4], kv[4];
                #pragma unroll
                for (int r = 0; r < 4; ++r)
                    qv[r] = *(const float4*)(qs + (ai0 + r) * AQ + 4 * dq);
                #pragma unroll
                for (int c = 0; c < 4; ++c)
                    kv[c] = *(const float4*)(ks + (tj + 16 * c) * AQ + 4 * dq);
                #pragma unroll
                for (int r = 0; r < 4; ++r) {
                    ull q01 = pk2(qv[r].x, qv[r].y), q23 = pk2(qv[r].z, qv[r].w);
                    #pragma unroll
                    for (int c = 0; c < 4; ++c) {
                        fma2(s2[r][c], q01, pk2(kv[c].x, kv[c].y));
                        fma2(s2[r][c], q23, pk2(kv[c].z, kv[c].w));
                    }
                }
            }
            #pragma unroll
            for (int r = 0; r < 4; ++r) {
                int i = ai0 + r;
                int r1 = i >> 3, c1 = i & 7;
                float sim[4];
                #pragma unroll
                for (int c = 0; c < 4; ++c) {
                    int j = tj + 16 * c;
                    int r2 = j >> 3, c2 = j & 7;
                    float2 p = up2(s2[r][c]);
                    sim[c] = p.x + p.y + mats[(r2 - r1 + 7) * 15 + (c2 - c1 + 7)];
                }
                float m = fmaxf(fmaxf(sim[0], sim[1]), fmaxf(sim[2], sim[3]));
                m = fmaxf(m, __shfl_xor_sync(0xffffffffu, m, 1));
                m = fmaxf(m, __shfl_xor_sync(0xffffffffu, m, 2));
                m = fmaxf(m, __shfl_xor_sync(0xffffffffu, m, 4));
                m = fmaxf(m, __shfl_xor_sync(0xffffffffu, m, 8));
                float e0 = __expf(sim[0] - m), e1 = __expf(sim[1] - m);
                float e2 = __expf(sim[2] - m), e3 = __expf(sim[3] - m);
                float s = e0 + e1 + e2 + e3;
                s += __shfl_xor_sync(0xffffffffu, s, 1);
                s += __shfl_xor_sync(0xffffffffu, s, 2);
                s += __shfl_xor_sync(0xffffffffu, s, 4);
                s += __shfl_xor_sync(0xffffffffu, s, 8);
                float inv = 1.f / s;
                as_[(ai0 + r) * AQ + tj]      = e0 * inv;
                as_[(ai0 + r) * AQ + tj + 16] = e1 * inv;
                as_[(ai0 + r) * AQ + tj + 32] = e2 * inv;
                as_[(ai0 + r) * AQ + tj + 48] = e3 * inv;
            }
        }
        __syncthreads();

        // ---- out = attn @ v ; store fp16 ----
        {
            ull o2[4][2];
            #pragma unroll
            for (int r = 0; r < 4; ++r) { o2[r][0] = 0ULL; o2[r][1] = 0ULL; }
            #pragma unroll 4
            for (int j = 0; j < 64; ++j) {
                float4 vv = *(const float4*)(vs + j * AQ + d0);
                ull vp0 = pk2(vv.x, vv.y), vp1 = pk2(vv.z, vv.w);
                #pragma unroll
                for (int r = 0; r < 4; ++r) {
                    float a = as_[(ai0 + r) * AQ + j];
                    ull pa = pk2(a, a);
                    fma2(o2[r][0], pa, vp0);
                    fma2(o2[r][1], pa, vp1);
                }
            }
            #pragma unroll
            for (int r = 0; r < 4; ++r) {
                float2 lo2 = up2(o2[r][0]), hi2 = up2(o2[r][1]);
                size_t off = ((size_t)b * NTOK + ai0 + r) * DIM + h * 64 + d0;
                *(__half2*)(g_ao_h + off)     = __floats2half2_rn(lo2.x, lo2.y);
                *(__half2*)(g_ao_h + off + 2) = __floats2half2_rn(hi2.x, hi2.y);
            }
        }
        __syncthreads();
    }
}

// ============================================================================
extern "C" void kernel_launch(void* const* d_in, const int* in_sizes, int n_in,
                              void* d_out, int out_size) {
    const float* x    = (const float*)d_in[0];
    const float* wqkv = (const float*)d_in[1];
    const float* wout = (const float*)d_in[2];
    const float* bout = (const float*)d_in[3];
    const float* Mat  = (const float*)d_in[4];
    float* y = (float*)d_out;

    static bool attr_set = false;
    if (!attr_set) {
        cudaFuncSetAttribute(gemm_kernel,
                             cudaFuncAttributeMaxDynamicSharedMemorySize, GSMEM);
        cudaFuncSetAttribute(attn_kernel,
                             cudaFuncAttributeMaxDynamicSharedMemorySize, ASMEM);
        attr_set = true;
    }

    prep_kernel<<<8192, 256>>>(x, wqkv, wout);
    gemm_kernel<<<dim3(QKDIM / 128, NROWS / 128), 256, GSMEM>>>(0, nullptr, y);
    attn_kernel<<<NB, 256, ASMEM>>>(Mat);
    gemm_kernel<<<dim3(DIM / 128, NROWS / 128), 256, GSMEM>>>(1, bout, y);
}